// round 12
// baseline (speedup 1.0000x reference)
#include <cuda_runtime.h>
#include <math.h>

// Problem constants
#define B_    16
#define C_    64
#define H_    224
#define W_    224
#define HW_   (H_ * W_)          // 50176
#define HW4_  (HW_ / 4)          // 12544
#define CHW4_ ((C_ * HW_) / 4)   // 802816

#define BAND   4                 // rows per band
#define NBAND  (H_ / BAND)       // 56 bands
#define NRED   (B_ * NBAND)      // 896 producer CTAs (= number of band flags)

// Occupancy cap: static smem (~18.9KB) + this dynamic pad -> ~34.3KB/CTA
// -> floor(228/34.3) = 6 CTAs/SM -> wave 1 = 888 slots ~= all 896 producers.
#define PAD_BYTES 15872

// Scratch (device globals — no allocation allowed)
__device__ float g_avg[B_ * HW_];        // 3.2 MB
__device__ float g_max[B_ * HW_];        // 3.2 MB
__device__ unsigned int g_flags[NRED];   // per-(batch,band) "feat ready"

// Fused-part smem tile geometry
#define HR    10                 // BAND + 6 halo rows
#define HC    230                // 224 + 6 halo cols
#define HCP   232                // padded row stride

// ---------------------------------------------------------------------------
// ONE kernel, two roles by blockIdx.x:
//   bid <  NRED : producer — channel mean+max of one (batch, 4-row band),
//                 fence, set flag. All producers occupy wave 1 alone.
//   bid >= NRED : consumer — wait on 3 band flags (scheduled only after
//                 producers drain, so waits are ~zero), then halo load ->
//                 7x7 conv -> sigmoid -> stream out = x * gate.
// ---------------------------------------------------------------------------
__global__ void __launch_bounds__(224) mega_kernel(
        const float* __restrict__ x,
        const float* __restrict__ conv_w,
        const float* __restrict__ conv_b,
        float* __restrict__ out) {
    extern __shared__ float s_pad[];         // occupancy pad (untouched)
    __shared__ float s_feat[2 * HR * HCP];   // 18.6 KB (consumer role)
    __shared__ float s_w[98];

    int bid = blockIdx.x;
    int t   = threadIdx.x;                   // 0..223
    int row = t / 56;                        // 0..3
    int p   = t - row * 56;                  // 0..55 (float4 position)

    const float4* x4 = (const float4*)x;

    if (bid < NRED) {
        // ================= PRODUCER =================
        int b    = bid / NBAND;
        int band = bid - b * NBAND;
        int h    = band * BAND + row;

        long base = (long)b * CHW4_ + h * 56 + p;

        float4 s = make_float4(0.f, 0.f, 0.f, 0.f);
        float4 m = make_float4(-INFINITY, -INFINITY, -INFINITY, -INFINITY);
#pragma unroll 8
        for (int c = 0; c < C_; c++) {
            float4 v = x4[base + (long)c * HW4_];
            s.x += v.x; s.y += v.y; s.z += v.z; s.w += v.w;
            m.x = fmaxf(m.x, v.x); m.y = fmaxf(m.y, v.y);
            m.z = fmaxf(m.z, v.z); m.w = fmaxf(m.w, v.w);
        }
        const float inv = 1.0f / (float)C_;
        s.x *= inv; s.y *= inv; s.z *= inv; s.w *= inv;

        int fidx = b * HW4_ + h * 56 + p;
        ((float4*)g_avg)[fidx] = s;          // cacheable: stay L2-hot
        ((float4*)g_max)[fidx] = m;

        __syncthreads();
        if (t == 0) {
            __threadfence();                 // feat visible before flag
            atomicExch(&g_flags[bid], 1u);
        }
    } else {
        // ================= CONSUMER =================
        int fb   = bid - NRED;
        int b    = fb / NBAND;
        int band = fb - b * NBAND;
        int h0   = band * BAND;

        if (t < 98) s_w[t] = conv_w[t];

        // Wait for the 3 producer bands covering rows h0-3 .. h0+6
        if (t < 3) {
            int bb = band - 1 + t;
            if (bb >= 0 && bb < NBAND) {
                while (atomicAdd(&g_flags[b * NBAND + bb], 0u) == 0u)
                    __nanosleep(128);
                __threadfence();             // acquire for feat reads
            }
        }
        __syncthreads();

        // Halo load: 2ch x 10r x 230c (L2-hot feat)
        const float* srcA = g_avg + b * HW_;
        const float* srcM = g_max + b * HW_;
        for (int i = t; i < 2 * HR * HC; i += 224) {
            int ch = i / (HR * HC);
            int rr = i - ch * (HR * HC);
            int r  = rr / HC;
            int cc = rr - r * HC;
            int gh = h0 + r - 3;
            int gw = cc - 3;
            float v = 0.f;
            if (gh >= 0 && gh < H_ && gw >= 0 && gw < W_)
                v = __ldg((ch == 0 ? srcA : srcM) + gh * W_ + gw);
            s_feat[ch * HR * HCP + r * HCP + cc] = v;
        }
        __syncthreads();

        // 7x7 conv + sigmoid for this thread's 4 outputs
        float a0 = conv_b[0], a1 = a0, a2 = a0, a3 = a0;
#pragma unroll
        for (int ch = 0; ch < 2; ch++) {
#pragma unroll
            for (int kh = 0; kh < 7; kh++) {
                const float* rp = s_feat + ch * HR * HCP + (row + kh) * HCP + 4 * p;
                float4 v0 = *(const float4*)(rp);       // LDS.128
                float4 v1 = *(const float4*)(rp + 4);
                float  e0 = rp[8];
                float  e1 = rp[9];
                float r_[10] = { v0.x, v0.y, v0.z, v0.w,
                                 v1.x, v1.y, v1.z, v1.w, e0, e1 };
                const float* wk = s_w + ch * 49 + kh * 7;
#pragma unroll
                for (int kw = 0; kw < 7; kw++) {
                    float wv = wk[kw];
                    a0 = fmaf(r_[kw + 0], wv, a0);
                    a1 = fmaf(r_[kw + 1], wv, a1);
                    a2 = fmaf(r_[kw + 2], wv, a2);
                    a3 = fmaf(r_[kw + 3], wv, a3);
                }
            }
        }

        float4 g;
        g.x = 1.0f / (1.0f + __expf(-a0));
        g.y = 1.0f / (1.0f + __expf(-a1));
        g.z = 1.0f / (1.0f + __expf(-a2));
        g.w = 1.0f / (1.0f + __expf(-a3));

        // Stream: out = x * gate across 64 channels (LDG/STG.128)
        long base4 = (long)b * CHW4_ + (h0 + row) * 56 + p;
        float4* o4 = (float4*)out;
#pragma unroll 8
        for (int c = 0; c < C_; c++) {
            long idx = base4 + (long)c * HW4_;
            float4 v = x4[idx];
            v.x *= g.x; v.y *= g.y; v.z *= g.z; v.w *= g.w;
            __stcs(o4 + idx, v);
        }
    }

    // keep the dynamic-smem pad alive (never executes; t < 224 always)
    if (t >= 100000) s_pad[0] = 1.0f;
}

// ---------------------------------------------------------------------------
extern "C" void kernel_launch(void* const* d_in, const int* in_sizes, int n_in,
                              void* d_out, int out_size) {
    const float* x      = (const float*)d_in[0];
    const float* conv_w = (const float*)d_in[1];
    const float* conv_b = (const float*)d_in[2];
    float* out = (float*)d_out;

    // Reset band flags (device globals persist across graph replays).
    void* flags_ptr = nullptr;
    cudaGetSymbolAddress(&flags_ptr, g_flags);
    cudaMemsetAsync(flags_ptr, 0, NRED * sizeof(unsigned int));

    // Single launch: 896 producers + 896 consumers; 6 CTAs/SM via smem pad.
    mega_kernel<<<2 * NRED, 224, PAD_BYTES>>>(x, conv_w, conv_b, out);
}

// round 13
// speedup vs baseline: 1.1300x; 1.1300x over previous
#include <cuda_runtime.h>
#include <math.h>

// Problem constants
#define B_    16
#define C_    64
#define H_    224
#define W_    224
#define HW_   (H_ * W_)          // 50176
#define CHW_  (C_ * HW_)         // 3211264
#define HW4_  (HW_ / 4)          // 12544
#define CHW4_ (CHW_ / 4)         // 802816

// Scratch (device globals — no allocation allowed)
__device__ float g_avg[B_ * HW_];   // 3.2 MB
__device__ float g_max[B_ * HW_];   // 3.2 MB

// ---------------------------------------------------------------------------
// Kernel 1: channel-wise mean + max reduce (proven: ~33us @ 80% DRAM).
// ---------------------------------------------------------------------------
__global__ void reduce_kernel(const float* __restrict__ x) {
    int idx = blockIdx.x * blockDim.x + threadIdx.x;   // float4 idx in [0, B_*HW4_)
    if (idx >= B_ * HW4_) return;
    int b = idx / HW4_;
    int p = idx - b * HW4_;

    const float4* x4 = (const float4*)x;
    long base = (long)b * CHW4_ + p;

    float4 s = make_float4(0.f, 0.f, 0.f, 0.f);
    float4 m = make_float4(-INFINITY, -INFINITY, -INFINITY, -INFINITY);

#pragma unroll 8
    for (int c = 0; c < C_; c++) {
        float4 v = x4[base + (long)c * HW4_];
        s.x += v.x; s.y += v.y; s.z += v.z; s.w += v.w;
        m.x = fmaxf(m.x, v.x); m.y = fmaxf(m.y, v.y);
        m.z = fmaxf(m.z, v.z); m.w = fmaxf(m.w, v.w);
    }
    const float inv = 1.0f / (float)C_;
    s.x *= inv; s.y *= inv; s.z *= inv; s.w *= inv;

    ((float4*)g_avg)[idx] = s;     // cacheable: keep feat L2-hot for K2
    ((float4*)g_max)[idx] = m;
}

// ---------------------------------------------------------------------------
// Kernel 2 (fused, PDL secondary): conv7x7 + sigmoid -> gate -> out = x*gate.
// Launched with programmatic stream serialization: CTAs come up and run the
// prologue (weights, indexing) during K1's tail; cudaGridDependencySynchronize
// gates only the feat-dependent halo reads.
// ---------------------------------------------------------------------------
#define BAND  4                 // output rows per CTA
#define HR    10                // BAND + 6 halo rows
#define HC    230               // 224 + 6 halo cols
#define HCP   232               // padded row stride (16B-aligned rows)

__global__ void __launch_bounds__(224) fused_gate_mul_kernel(
        const float* __restrict__ x,
        const float* __restrict__ conv_w,
        const float* __restrict__ conv_b,
        float* __restrict__ out) {
    __shared__ float s_feat[2 * HR * HCP];   // 18.6 KB
    __shared__ float s_w[98];

    int t  = threadIdx.x;            // 0..223
    int h0 = blockIdx.x * BAND;      // 56 bands
    int b  = blockIdx.y;             // 16 batches

    // Pre-dependency work: conv_w/conv_b are harness inputs (not produced by
    // K1), safe to read before the dependency sync.
    if (t < 98) s_w[t] = conv_w[t];
    float bias = conv_b[0];

    int row = t / 56;                // 0..3
    int w4  = t - row * 56;          // 0..55

    // Wait for K1's memory to be visible, then read feat.
    cudaGridDependencySynchronize();

    // Halo load: 2ch x 10r x 230c (L2-hot feat)
    const float* srcA = g_avg + b * HW_;
    const float* srcM = g_max + b * HW_;
    for (int i = t; i < 2 * HR * HC; i += 224) {
        int ch = i / (HR * HC);
        int rr = i - ch * (HR * HC);
        int r  = rr / HC;
        int cc = rr - r * HC;
        int gh = h0 + r - 3;
        int gw = cc - 3;
        float v = 0.f;
        if (gh >= 0 && gh < H_ && gw >= 0 && gw < W_)
            v = __ldg((ch == 0 ? srcA : srcM) + gh * W_ + gw);
        s_feat[ch * HR * HCP + r * HCP + cc] = v;
    }
    __syncthreads();

    // 7x7 conv + sigmoid for this thread's 4 outputs
    float a0 = bias, a1 = bias, a2 = bias, a3 = bias;
#pragma unroll
    for (int ch = 0; ch < 2; ch++) {
#pragma unroll
        for (int kh = 0; kh < 7; kh++) {
            const float* rp = s_feat + ch * HR * HCP + (row + kh) * HCP + 4 * w4;
            float4 v0 = *(const float4*)(rp);       // LDS.128 (16B-aligned)
            float4 v1 = *(const float4*)(rp + 4);
            float  e0 = rp[8];
            float  e1 = rp[9];
            float r_[10] = { v0.x, v0.y, v0.z, v0.w,
                             v1.x, v1.y, v1.z, v1.w, e0, e1 };
            const float* wk = s_w + ch * 49 + kh * 7;
#pragma unroll
            for (int kw = 0; kw < 7; kw++) {
                float wv = wk[kw];
                a0 = fmaf(r_[kw + 0], wv, a0);
                a1 = fmaf(r_[kw + 1], wv, a1);
                a2 = fmaf(r_[kw + 2], wv, a2);
                a3 = fmaf(r_[kw + 3], wv, a3);
            }
        }
    }

    float4 g;
    g.x = 1.0f / (1.0f + __expf(-a0));
    g.y = 1.0f / (1.0f + __expf(-a1));
    g.z = 1.0f / (1.0f + __expf(-a2));
    g.w = 1.0f / (1.0f + __expf(-a3));

    // Stream: out = x * gate across 64 channels (LDG/STG.128, 32 regs)
    long base4 = (long)b * CHW4_ + (h0 + row) * 56 + w4;
    const float4* x4 = (const float4*)x;
    float4* o4 = (float4*)out;

#pragma unroll 8
    for (int c = 0; c < C_; c++) {
        long idx = base4 + (long)c * HW4_;
        float4 v = x4[idx];
        v.x *= g.x; v.y *= g.y; v.z *= g.z; v.w *= g.w;
        __stcs(o4 + idx, v);
    }
}

// ---------------------------------------------------------------------------
extern "C" void kernel_launch(void* const* d_in, const int* in_sizes, int n_in,
                              void* d_out, int out_size) {
    const float* x      = (const float*)d_in[0];
    const float* conv_w = (const float*)d_in[1];
    const float* conv_b = (const float*)d_in[2];
    float* out = (float*)d_out;

    // K1: channel reduce (at DRAM roofline)
    {
        int n = B_ * HW4_;                   // 200704 threads
        reduce_kernel<<<(n + 255) / 256, 256>>>(x);
    }
    // K2: fused kernel as a PDL secondary — overlaps launch+prologue with K1
    // tail; in-kernel cudaGridDependencySynchronize() guards the feat reads.
    {
        cudaLaunchAttribute attrs[1];
        attrs[0].id = cudaLaunchAttributeProgrammaticStreamSerialization;
        attrs[0].val.programmaticStreamSerializationAllowed = 1;

        cudaLaunchConfig_t cfg = {};
        cfg.gridDim  = dim3(H_ / BAND, B_);  // (56, 16) = 896 CTAs
        cfg.blockDim = dim3(224);
        cfg.dynamicSmemBytes = 0;
        cfg.stream = 0;
        cfg.attrs = attrs;
        cfg.numAttrs = 1;

        cudaLaunchKernelEx(&cfg, fused_gate_mul_kernel, x, conv_w, conv_b, out);
    }
}